// round 8
// baseline (speedup 1.0000x reference)
#include <cuda_runtime.h>
#include <cstdint>

#define B_ 8
#define N_ 4096
#define M_ 4096
#define C_ 128

#define TMT 128                 // CTA tile M (set1 rows)
#define TNT 128                 // CTA tile N (set2 rows)
#define KC 32                   // k-chunk
#define NCHUNK (C_ / KC)        // 4
#define PADK 36                 // smem row stride in floats (conflict-free frags)
#define ABUF_FLOATS (TMT * PADK)        // 4608
#define BUF_FLOATS (2 * ABUF_FLOATS)    // A + B per stage

// ---------------- device scratch (allocation-free rule) ----------------
__device__ unsigned int g_rowmin[B_ * N_];
__device__ unsigned int g_colmin[B_ * M_];
__device__ float g_sq1[B_ * N_];
__device__ float g_sq2[B_ * M_];

// ---------------- PTX helpers -----------------------------------------
__device__ __forceinline__ uint32_t smem_u32(const void* p) {
    uint32_t a;
    asm("{ .reg .u64 t; cvta.to.shared.u64 t, %1; cvt.u32.u64 %0, t; }"
        : "=r"(a) : "l"(p));
    return a;
}
#define CP_ASYNC16(d, s) \
    asm volatile("cp.async.cg.shared.global [%0], [%1], 16;" :: "r"(d), "l"(s))
#define CP_COMMIT() asm volatile("cp.async.commit_group;" ::: "memory")
#define CP_WAIT1()  asm volatile("cp.async.wait_group 1;" ::: "memory")

// round-to-nearest fp32 -> tf32 (kills RZ truncation bias of raw-bit reuse)
__device__ __forceinline__ uint32_t cvt_tf32(float x) {
    uint32_t r;
    asm("cvt.rna.tf32.f32 %0, %1;" : "=r"(r) : "f"(x));
    return r;
}

// m16n8k8 tf32 mma: D = A*B + D, fp32 accumulate. Plain-target instruction.
__device__ __forceinline__ void mma_tf32(float& c0, float& c1, float& c2, float& c3,
                                         uint32_t a0, uint32_t a1, uint32_t a2, uint32_t a3,
                                         uint32_t b0, uint32_t b1) {
    asm volatile(
        "mma.sync.aligned.m16n8k8.row.col.f32.tf32.tf32.f32 "
        "{%0,%1,%2,%3}, {%4,%5,%6,%7}, {%8,%9}, {%0,%1,%2,%3};"
        : "+f"(c0), "+f"(c1), "+f"(c2), "+f"(c3)
        : "r"(a0), "r"(a1), "r"(a2), "r"(a3), "r"(b0), "r"(b1));
}

// ---------------------------------------------------------------------------
// Kernel 1: squared norms + init min arrays
// ---------------------------------------------------------------------------
__global__ void norms_kernel(const float* __restrict__ s1,
                             const float* __restrict__ s2) {
    int idx = blockIdx.x * blockDim.x + threadIdx.x;
    const int total = B_ * N_;
    if (idx < total) {
        const float4* p = (const float4*)(s1 + (size_t)idx * C_);
        float s = 0.f;
#pragma unroll
        for (int i = 0; i < C_ / 4; i++) {
            float4 v = p[i];
            s += v.x * v.x + v.y * v.y + v.z * v.z + v.w * v.w;
        }
        g_sq1[idx] = s;
        g_rowmin[idx] = 0x7f800000u;
    } else if (idx < 2 * total) {
        int j = idx - total;
        const float4* p = (const float4*)(s2 + (size_t)j * C_);
        float s = 0.f;
#pragma unroll
        for (int i = 0; i < C_ / 4; i++) {
            float4 v = p[i];
            s += v.x * v.x + v.y * v.y + v.z * v.z + v.w * v.w;
        }
        g_sq2[j] = s;
        g_colmin[j] = 0x7f800000u;
    }
}

// ---------------------------------------------------------------------------
// Kernel 2: 128x128 tile via tf32 mma.sync, cp.async double-buffered K-chunks,
// register accumulators, fused d2 + row/col min epilogue.
// 8 warps: warpRow = wid>>2 (2 x 64 rows), warpCol = wid&3 (4 x 32 cols).
// Each warp: 4 m-frags (16 rows) x 4 n-frags (8 cols) of m16n8k8.
// ---------------------------------------------------------------------------
__global__ void __launch_bounds__(256, 2)
hausdorff_mma_kernel(const float* __restrict__ s1, const float* __restrict__ s2) {
    extern __shared__ float sm[];   // [2][A 128*36 | B 128*36]
    __shared__ unsigned int s_rmin[TMT];
    __shared__ unsigned int s_cmin[TNT];
    __shared__ float s_sq1[TMT];
    __shared__ float s_sq2[TNT];

    const int tid = threadIdx.x;
    const int wid = tid >> 5;
    const int lane = tid & 31;
    const int g = lane >> 2;        // group id 0..7
    const int t = lane & 3;         // thread-in-group
    const int wr = wid >> 2;        // warp row 0..1
    const int wc = wid & 3;         // warp col 0..3
    const int b = blockIdx.z;
    const int row0 = blockIdx.x * TMT;
    const int col0 = blockIdx.y * TNT;

    const float* A = s1 + ((size_t)b * N_ + row0) * C_;
    const float* Bp = s2 + ((size_t)b * M_ + col0) * C_;

    const uint32_t smbase = smem_u32(sm);

    if (tid < TMT) {
        s_rmin[tid] = 0x7f800000u;
        s_cmin[tid] = 0x7f800000u;
        s_sq1[tid] = g_sq1[(size_t)b * N_ + row0 + tid];
        s_sq2[tid] = g_sq2[(size_t)b * M_ + col0 + tid];
    }

    // cp.async mapping: 1024 float4 per matrix per chunk; 256 threads -> 4 each.
    // f = q*256+tid: row = f>>3 (8 float4 per 32-float row), kq = (f&7)*4.
    auto issue_chunk = [&](int c, int buf) {
        const int k0 = c * KC;
        const uint32_t abase = smbase + (uint32_t)buf * BUF_FLOATS * 4u;
        const uint32_t bbase = abase + ABUF_FLOATS * 4u;
#pragma unroll
        for (int q = 0; q < 4; q++) {
            int f = q * 256 + tid;
            int rr = f >> 3;
            int kq = (f & 7) * 4;
            CP_ASYNC16(abase + (uint32_t)(rr * PADK + kq) * 4u,
                       A + (size_t)rr * C_ + k0 + kq);
        }
#pragma unroll
        for (int q = 0; q < 4; q++) {
            int f = q * 256 + tid;
            int rr = f >> 3;
            int kq = (f & 7) * 4;
            CP_ASYNC16(bbase + (uint32_t)(rr * PADK + kq) * 4u,
                       Bp + (size_t)rr * C_ + k0 + kq);
        }
    };

    // prologue: chunk 0 -> buf 0
    issue_chunk(0, 0);
    CP_COMMIT();

    float acc[4][4][4];
#pragma unroll
    for (int mf = 0; mf < 4; mf++)
#pragma unroll
        for (int nf = 0; nf < 4; nf++)
#pragma unroll
            for (int e = 0; e < 4; e++) acc[mf][nf][e] = 0.f;

#pragma unroll 1
    for (int c = 0; c < NCHUNK; c++) {
        if (c + 1 < NCHUNK) issue_chunk(c + 1, (c + 1) & 1);
        CP_COMMIT();
        CP_WAIT1();          // chunk c resident (all earlier groups done)
        __syncthreads();

        const float* As = sm + (size_t)(c & 1) * BUF_FLOATS;
        const float* Bs = As + ABUF_FLOATS;

#pragma unroll
        for (int k8 = 0; k8 < KC / 8; k8++) {
            const int kb = k8 * 8;
            uint32_t af[4][4], bf[4][2];
#pragma unroll
            for (int mf = 0; mf < 4; mf++) {
                const int r = wr * 64 + mf * 16 + g;
                af[mf][0] = cvt_tf32(As[r * PADK + kb + t]);
                af[mf][1] = cvt_tf32(As[(r + 8) * PADK + kb + t]);
                af[mf][2] = cvt_tf32(As[r * PADK + kb + t + 4]);
                af[mf][3] = cvt_tf32(As[(r + 8) * PADK + kb + t + 4]);
            }
#pragma unroll
            for (int nf = 0; nf < 4; nf++) {
                const int n = wc * 32 + nf * 8 + g;
                bf[nf][0] = cvt_tf32(Bs[n * PADK + kb + t]);
                bf[nf][1] = cvt_tf32(Bs[n * PADK + kb + t + 4]);
            }
#pragma unroll
            for (int mf = 0; mf < 4; mf++)
#pragma unroll
                for (int nf = 0; nf < 4; nf++)
                    mma_tf32(acc[mf][nf][0], acc[mf][nf][1],
                             acc[mf][nf][2], acc[mf][nf][3],
                             af[mf][0], af[mf][1], af[mf][2], af[mf][3],
                             bf[nf][0], bf[nf][1]);
        }
        __syncthreads();     // compute(c) done before buf (c&1) is refilled
    }

    // ---- epilogue: d2 = sq1 + sq2 - 2*ip; per-thread row/col mins ----
    // acc[mf][nf]: rows wr*64+mf*16+{g,g+8}, cols wc*32+nf*8+{2t,2t+1}
    float rmin[4][2], cmin[4][2];
#pragma unroll
    for (int i = 0; i < 4; i++) {
        rmin[i][0] = rmin[i][1] = __int_as_float(0x7f800000);
        cmin[i][0] = cmin[i][1] = __int_as_float(0x7f800000);
    }
#pragma unroll
    for (int mf = 0; mf < 4; mf++) {
        const int r = wr * 64 + mf * 16 + g;
        const float q1a = s_sq1[r], q1b = s_sq1[r + 8];
#pragma unroll
        for (int nf = 0; nf < 4; nf++) {
            const int n = wc * 32 + nf * 8 + 2 * t;
            const float q2a = s_sq2[n], q2b = s_sq2[n + 1];
            float d00 = fmaxf(fmaf(-2.f, acc[mf][nf][0], q1a + q2a), 0.f);
            float d01 = fmaxf(fmaf(-2.f, acc[mf][nf][1], q1a + q2b), 0.f);
            float d10 = fmaxf(fmaf(-2.f, acc[mf][nf][2], q1b + q2a), 0.f);
            float d11 = fmaxf(fmaf(-2.f, acc[mf][nf][3], q1b + q2b), 0.f);
            rmin[mf][0] = fminf(rmin[mf][0], fminf(d00, d01));
            rmin[mf][1] = fminf(rmin[mf][1], fminf(d10, d11));
            cmin[nf][0] = fminf(cmin[nf][0], fminf(d00, d10));
            cmin[nf][1] = fminf(cmin[nf][1], fminf(d01, d11));
        }
    }
#pragma unroll
    for (int mf = 0; mf < 4; mf++) {
        const int r = wr * 64 + mf * 16 + g;
        atomicMin(&s_rmin[r], __float_as_uint(rmin[mf][0]));
        atomicMin(&s_rmin[r + 8], __float_as_uint(rmin[mf][1]));
    }
#pragma unroll
    for (int nf = 0; nf < 4; nf++) {
        const int n = wc * 32 + nf * 8 + 2 * t;
        atomicMin(&s_cmin[n], __float_as_uint(cmin[nf][0]));
        atomicMin(&s_cmin[n + 1], __float_as_uint(cmin[nf][1]));
    }
    __syncthreads();

    if (tid < TMT)
        atomicMin(&g_rowmin[(size_t)b * N_ + row0 + tid], s_rmin[tid]);
    else if (tid < TMT + TNT) {
        const int n = tid - TMT;
        atomicMin(&g_colmin[(size_t)b * M_ + col0 + n], s_cmin[n]);
    }
}

// ---------------------------------------------------------------------------
// Kernel 3: out[b] = mean_i sqrt(rowmin) + mean_j sqrt(colmin)
// ---------------------------------------------------------------------------
__global__ void reduce_kernel(float* __restrict__ out) {
    const int b = blockIdx.x;
    __shared__ float red[256];
    float s = 0.f;
    for (int i = threadIdx.x; i < N_; i += 256)
        s += sqrtf(__uint_as_float(g_rowmin[b * N_ + i]));
    for (int j = threadIdx.x; j < M_; j += 256)
        s += sqrtf(__uint_as_float(g_colmin[b * M_ + j]));
    red[threadIdx.x] = s;
    __syncthreads();
    for (int off = 128; off > 0; off >>= 1) {
        if (threadIdx.x < off) red[threadIdx.x] += red[threadIdx.x + off];
        __syncthreads();
    }
    if (threadIdx.x == 0) out[b] = red[0] * (1.f / N_);  // N_ == M_
}

// ---------------------------------------------------------------------------
extern "C" void kernel_launch(void* const* d_in, const int* in_sizes, int n_in,
                              void* d_out, int out_size) {
    const float* set1 = (const float*)d_in[0];
    const float* set2 = (const float*)d_in[1];
    float* out = (float*)d_out;

    const int SMEM = 2 * BUF_FLOATS * 4;   // 73728 B
    cudaFuncSetAttribute(hausdorff_mma_kernel,
                         cudaFuncAttributeMaxDynamicSharedMemorySize, SMEM);

    norms_kernel<<<(2 * B_ * N_ + 255) / 256, 256>>>(set1, set2);
    dim3 grid(N_ / TMT, M_ / TNT, B_);     // (32, 32, 8)
    hausdorff_mma_kernel<<<grid, 256, SMEM>>>(set1, set2);
    reduce_kernel<<<B_, 256>>>(out);
}

// round 14
// speedup vs baseline: 1.5452x; 1.5452x over previous
#include <cuda_runtime.h>
#include <cuda_fp16.h>
#include <cstdint>

#define B_ 8
#define N_ 4096
#define M_ 4096
#define C_ 128

#define TMT 128                 // CTA tile M (set1 rows)
#define TNT 128                 // CTA tile N (set2 rows)
#define KC 32                   // k-chunk (halfs)
#define NCHUNK (C_ / KC)        // 4
#define PADH 40                 // smem row stride in halfs (conflict-free frags)
#define ABUF_HALFS (TMT * PADH)         // 5120 halfs = 10240 B
#define BUF_HALFS (2 * ABUF_HALFS)      // A + B per stage

// ---------------- device scratch (allocation-free rule) ----------------
__device__ unsigned int g_rowmin[B_ * N_];
__device__ unsigned int g_colmin[B_ * M_];
__device__ float g_sq1[B_ * N_];
__device__ float g_sq2[B_ * M_];
__device__ __half g_h1[B_ * N_ * C_];   // fp16 copies (8.4 MB each)
__device__ __half g_h2[B_ * M_ * C_];

// ---------------- PTX helpers -----------------------------------------
__device__ __forceinline__ uint32_t smem_u32(const void* p) {
    uint32_t a;
    asm("{ .reg .u64 t; cvta.to.shared.u64 t, %1; cvt.u32.u64 %0, t; }"
        : "=r"(a) : "l"(p));
    return a;
}
#define CP_ASYNC16(d, s) \
    asm volatile("cp.async.cg.shared.global [%0], [%1], 16;" :: "r"(d), "l"(s))
#define CP_COMMIT() asm volatile("cp.async.commit_group;" ::: "memory")
#define CP_WAIT1()  asm volatile("cp.async.wait_group 1;" ::: "memory")

// m16n8k16 fp16 mma, fp32 accumulate. Plain-target instruction.
__device__ __forceinline__ void mma_f16(float& c0, float& c1, float& c2, float& c3,
                                        uint32_t a0, uint32_t a1, uint32_t a2, uint32_t a3,
                                        uint32_t b0, uint32_t b1) {
    asm volatile(
        "mma.sync.aligned.m16n8k16.row.col.f32.f16.f16.f32 "
        "{%0,%1,%2,%3}, {%4,%5,%6,%7}, {%8,%9}, {%0,%1,%2,%3};"
        : "+f"(c0), "+f"(c1), "+f"(c2), "+f"(c3)
        : "r"(a0), "r"(a1), "r"(a2), "r"(a3), "r"(b0), "r"(b1));
}

// ---------------------------------------------------------------------------
// Kernel 1: squared norms (fp32) + fp16 conversion + init min arrays.
// ONE WARP PER ROW (coalesced): 32 lanes x float4 = 128 floats; fp16 stores
// as coalesced uint2; norm via shfl butterfly. (Round-8 ncu: thread-per-row
// version ran at 2.5TB/s due to 512B intra-warp stride.)
// ---------------------------------------------------------------------------
__global__ void prep_kernel(const float* __restrict__ s1,
                            const float* __restrict__ s2) {
    const int w = (blockIdx.x * blockDim.x + threadIdx.x) >> 5;  // global warp
    const int lane = threadIdx.x & 31;
    const int total = B_ * N_;
    if (w >= 2 * total) return;
    const float* src;
    __half* dst;
    float* sqv;
    unsigned int* mn;
    int j;
    if (w < total) {
        j = w; src = s1; dst = g_h1; sqv = g_sq1; mn = g_rowmin;
    } else {
        j = w - total; src = s2; dst = g_h2; sqv = g_sq2; mn = g_colmin;
    }

    float4 v = ((const float4*)(src + (size_t)j * C_))[lane];
    float s = v.x * v.x + v.y * v.y + v.z * v.z + v.w * v.w;
    __half2 h0 = __floats2half2_rn(v.x, v.y);
    __half2 h1 = __floats2half2_rn(v.z, v.w);
    uint2 u;
    u.x = *(uint32_t*)&h0;
    u.y = *(uint32_t*)&h1;
    ((uint2*)(dst + (size_t)j * C_))[lane] = u;

#pragma unroll
    for (int off = 16; off > 0; off >>= 1)
        s += __shfl_xor_sync(0xffffffffu, s, off);
    if (lane == 0) {
        sqv[j] = s;
        mn[j] = 0x7f800000u;
    }
}

// ---------------------------------------------------------------------------
// Kernel 2: 128x128 tile via fp16 mma.sync (fp32 accum), cp.async double-
// buffered K-chunks, register accumulators, fused d2 + row/col min epilogue.
// 8 warps: wr = wid>>2 (2 x 64 rows), wc = wid&3 (4 x 32 cols).
// Each warp: 4 m-frags (16 rows) x 4 n-frags (8 cols) of m16n8k16.
// ---------------------------------------------------------------------------
__global__ void __launch_bounds__(256, 2)
hausdorff_mma_kernel() {
    extern __shared__ __half sm[];   // [2][A 128*40 | B 128*40] halfs
    __shared__ unsigned int s_rmin[TMT];
    __shared__ unsigned int s_cmin[TNT];
    __shared__ float s_sq1[TMT];
    __shared__ float s_sq2[TNT];

    const int tid = threadIdx.x;
    const int wid = tid >> 5;
    const int lane = tid & 31;
    const int g = lane >> 2;        // group id 0..7
    const int t = lane & 3;         // thread-in-group
    const int wr = wid >> 2;        // warp row 0..1
    const int wc = wid & 3;         // warp col 0..3
    const int b = blockIdx.z;
    const int row0 = blockIdx.x * TMT;
    const int col0 = blockIdx.y * TNT;

    const __half* A = g_h1 + ((size_t)b * N_ + row0) * C_;
    const __half* Bp = g_h2 + ((size_t)b * M_ + col0) * C_;

    const uint32_t smbase = smem_u32(sm);

    if (tid < TMT) {
        s_rmin[tid] = 0x7f800000u;
        s_cmin[tid] = 0x7f800000u;
        s_sq1[tid] = g_sq1[(size_t)b * N_ + row0 + tid];
        s_sq2[tid] = g_sq2[(size_t)b * M_ + col0 + tid];
    }

    // cp.async: per chunk per matrix 128 rows x 32 halfs = 512 x 16B;
    // 256 threads -> 2 each. f = q*256+tid: row = f>>2, k8 = (f&3)*8.
    auto issue_chunk = [&](int c, int buf) {
        const int k0 = c * KC;
        const uint32_t abase = smbase + (uint32_t)buf * BUF_HALFS * 2u;
        const uint32_t bbase = abase + ABUF_HALFS * 2u;
#pragma unroll
        for (int q = 0; q < 2; q++) {
            int f = q * 256 + tid;
            int rr = f >> 2;
            int k8 = (f & 3) * 8;
            CP_ASYNC16(abase + (uint32_t)(rr * PADH + k8) * 2u,
                       A + (size_t)rr * C_ + k0 + k8);
        }
#pragma unroll
        for (int q = 0; q < 2; q++) {
            int f = q * 256 + tid;
            int rr = f >> 2;
            int k8 = (f & 3) * 8;
            CP_ASYNC16(bbase + (uint32_t)(rr * PADH + k8) * 2u,
                       Bp + (size_t)rr * C_ + k0 + k8);
        }
    };

    issue_chunk(0, 0);
    CP_COMMIT();

    float acc[4][4][4];
#pragma unroll
    for (int mf = 0; mf < 4; mf++)
#pragma unroll
        for (int nf = 0; nf < 4; nf++)
#pragma unroll
            for (int e = 0; e < 4; e++) acc[mf][nf][e] = 0.f;

#pragma unroll 1
    for (int c = 0; c < NCHUNK; c++) {
        if (c + 1 < NCHUNK) issue_chunk(c + 1, (c + 1) & 1);
        CP_COMMIT();
        CP_WAIT1();          // chunk c resident
        __syncthreads();

        const __half* As = sm + (size_t)(c & 1) * BUF_HALFS;
        const __half* Bs = As + ABUF_HALFS;

#pragma unroll
        for (int s = 0; s < KC / 16; s++) {     // 2 k16 steps per chunk
            const int kb = s * 16;
            uint32_t af[4][4], bf[4][2];
#pragma unroll
            for (int mf = 0; mf < 4; mf++) {
                const int r = wr * 64 + mf * 16 + g;
                af[mf][0] = *(const uint32_t*)&As[r * PADH + kb + 2 * t];
                af[mf][1] = *(const uint32_t*)&As[(r + 8) * PADH + kb + 2 * t];
                af[mf][2] = *(const uint32_t*)&As[r * PADH + kb + 2 * t + 8];
                af[mf][3] = *(const uint32_t*)&As[(r + 8) * PADH + kb + 2 * t + 8];
            }
#pragma unroll
            for (int nf = 0; nf < 4; nf++) {
                const int n = wc * 32 + nf * 8 + g;
                bf[nf][0] = *(const uint32_t*)&Bs[n * PADH + kb + 2 * t];
                bf[nf][1] = *(const uint32_t*)&Bs[n * PADH + kb + 2 * t + 8];
            }
#pragma unroll
            for (int mf = 0; mf < 4; mf++)
#pragma unroll
                for (int nf = 0; nf < 4; nf++)
                    mma_f16(acc[mf][nf][0], acc[mf][nf][1],
                            acc[mf][nf][2], acc[mf][nf][3],
                            af[mf][0], af[mf][1], af[mf][2], af[mf][3],
                            bf[nf][0], bf[nf][1]);
        }
        __syncthreads();     // compute(c) done before buf (c&1) refilled
    }

    // ---- epilogue: d2 = sq1 + sq2 - 2*ip; per-thread row/col mins ----
    // acc[mf][nf]: rows wr*64+mf*16+{g,g+8}, cols wc*32+nf*8+{2t,2t+1}
    float rmin[4][2], cmin[4][2];
#pragma unroll
    for (int i = 0; i < 4; i++) {
        rmin[i][0] = rmin[i][1] = __int_as_float(0x7f800000);
        cmin[i][0] = cmin[i][1] = __int_as_float(0x7f800000);
    }
#pragma unroll
    for (int mf = 0; mf < 4; mf++) {
        const int r = wr * 64 + mf * 16 + g;
        const float q1a = s_sq1[r], q1b = s_sq1[r + 8];
#pragma unroll
        for (int nf = 0; nf < 4; nf++) {
            const int n = wc * 32 + nf * 8 + 2 * t;
            const float q2a = s_sq2[n], q2b = s_sq2[n + 1];
            float d00 = fmaxf(fmaf(-2.f, acc[mf][nf][0], q1a + q2a), 0.f);
            float d01 = fmaxf(fmaf(-2.f, acc[mf][nf][1], q1a + q2b), 0.f);
            float d10 = fmaxf(fmaf(-2.f, acc[mf][nf][2], q1b + q2a), 0.f);
            float d11 = fmaxf(fmaf(-2.f, acc[mf][nf][3], q1b + q2b), 0.f);
            rmin[mf][0] = fminf(rmin[mf][0], fminf(d00, d01));
            rmin[mf][1] = fminf(rmin[mf][1], fminf(d10, d11));
            cmin[nf][0] = fminf(cmin[nf][0], fminf(d00, d10));
            cmin[nf][1] = fminf(cmin[nf][1], fminf(d01, d11));
        }
    }
#pragma unroll
    for (int mf = 0; mf < 4; mf++) {
        const int r = wr * 64 + mf * 16 + g;
        atomicMin(&s_rmin[r], __float_as_uint(rmin[mf][0]));
        atomicMin(&s_rmin[r + 8], __float_as_uint(rmin[mf][1]));
    }
#pragma unroll
    for (int nf = 0; nf < 4; nf++) {
        const int n = wc * 32 + nf * 8 + 2 * t;
        atomicMin(&s_cmin[n], __float_as_uint(cmin[nf][0]));
        atomicMin(&s_cmin[n + 1], __float_as_uint(cmin[nf][1]));
    }
    __syncthreads();

    if (tid < TMT)
        atomicMin(&g_rowmin[(size_t)b * N_ + row0 + tid], s_rmin[tid]);
    else if (tid < TMT + TNT) {
        const int n = tid - TMT;
        atomicMin(&g_colmin[(size_t)b * M_ + col0 + n], s_cmin[n]);
    }
}

// ---------------------------------------------------------------------------
// Kernel 3: out[b] = mean_i sqrt(rowmin) + mean_j sqrt(colmin)
// ---------------------------------------------------------------------------
__global__ void reduce_kernel(float* __restrict__ out) {
    const int b = blockIdx.x;
    __shared__ float red[256];
    float s = 0.f;
    for (int i = threadIdx.x; i < N_; i += 256)
        s += sqrtf(__uint_as_float(g_rowmin[b * N_ + i]));
    for (int j = threadIdx.x; j < M_; j += 256)
        s += sqrtf(__uint_as_float(g_colmin[b * M_ + j]));
    red[threadIdx.x] = s;
    __syncthreads();
    for (int off = 128; off > 0; off >>= 1) {
        if (threadIdx.x < off) red[threadIdx.x] += red[threadIdx.x + off];
        __syncthreads();
    }
    if (threadIdx.x == 0) out[b] = red[0] * (1.f / N_);  // N_ == M_
}

// ---------------------------------------------------------------------------
extern "C" void kernel_launch(void* const* d_in, const int* in_sizes, int n_in,
                              void* d_out, int out_size) {
    const float* set1 = (const float*)d_in[0];
    const float* set2 = (const float*)d_in[1];
    float* out = (float*)d_out;

    const int SMEM = 2 * BUF_HALFS * 2;    // 40960 B
    cudaFuncSetAttribute(hausdorff_mma_kernel,
                         cudaFuncAttributeMaxDynamicSharedMemorySize, SMEM);

    // one warp per row: 2*B*N rows, 8 warps per 256-thread block
    prep_kernel<<<(2 * B_ * N_) / 8, 256>>>(set1, set2);
    dim3 grid(N_ / TMT, M_ / TNT, B_);     // (32, 32, 8)
    hausdorff_mma_kernel<<<grid, 256, SMEM>>>();
    reduce_kernel<<<B_, 256>>>(out);
}